// round 2
// baseline (speedup 1.0000x reference)
#include <cuda_runtime.h>
#include <cuda_bf16.h>
#include <math_constants.h>

// ---------------------------------------------------------------------------
// MultiHeadAttention: x[2,2048,2048] fp32, 4x W[2048,2048]
//   q/k/v = (x@W).reshape(B,S,16,128) -> [B,16,S,128]
//   causal softmax(q k^T / sqrt(128)) @ v -> [B,S,2048] @ Wo
// Round 1: fp32 SIMT baseline; fixed smem pad 1->4 floats (float4 alignment).
// ---------------------------------------------------------------------------

#define BATCH   2
#define SEQ     2048
#define HID     2048
#define NH      16
#define HD      128
#define MTOT    (BATCH * SEQ)          // 4096
#define PAD     4                      // float4-safe smem pad

// scratch: Q,K,V in [B*NH, S, HD]; attn out in [B, S, HID]
__device__ float g_Q[MTOT * HID];
__device__ float g_K[MTOT * HID];
__device__ float g_V[MTOT * HID];
__device__ float g_A[MTOT * HID];

// ---------------------------------------------------------------------------
// SGEMM: C[M,N] = A[M,K] * B[K,N]  (row-major). 128x128x8 tile, 256 thr, 8x8.
// permute=1: write C in [B*NH, S, HD] layout (fused head transpose).
// ---------------------------------------------------------------------------
#define GBM 128
#define GBN 128
#define GBK 8

__global__ __launch_bounds__(256, 2)
void sgemm_kernel(const float* __restrict__ A, const float* __restrict__ B,
                  float* __restrict__ C, int M, int N, int K, int permute)
{
    __shared__ float As[GBK][GBM];      // transposed A tile
    __shared__ float Bs[GBK][GBN];

    const int t  = threadIdx.x;
    const int tx = t & 15;              // 0..15 -> col groups of 8
    const int ty = t >> 4;              // 0..15 -> row groups of 8
    const int bn = blockIdx.x * GBN;
    const int bm = blockIdx.y * GBM;

    // A tile loads: 128 rows x 8 cols = 256 float4 (2 per row)
    const int arow = t >> 1;            // 0..127
    const int acol = (t & 1) * 4;       // 0 or 4
    // B tile loads: 8 rows x 128 cols = 256 float4
    const int brow = t >> 5;            // 0..7
    const int bcol = (t & 31) * 4;      // 0..124

    const float* Ag = A + (size_t)(bm + arow) * K + acol;
    const float* Bg = B + (size_t)brow * N + bn + bcol;

    float acc[8][8];
#pragma unroll
    for (int i = 0; i < 8; i++)
#pragma unroll
        for (int j = 0; j < 8; j++) acc[i][j] = 0.f;

    for (int k0 = 0; k0 < K; k0 += GBK) {
        float4 a4 = *(const float4*)Ag;  Ag += GBK;
        float4 b4 = *(const float4*)Bg;  Bg += (size_t)GBK * N;

        As[acol + 0][arow] = a4.x;
        As[acol + 1][arow] = a4.y;
        As[acol + 2][arow] = a4.z;
        As[acol + 3][arow] = a4.w;
        *(float4*)&Bs[brow][bcol] = b4;
        __syncthreads();

#pragma unroll
        for (int k = 0; k < GBK; k++) {
            float4 a0 = *(const float4*)&As[k][ty * 8];
            float4 a1 = *(const float4*)&As[k][ty * 8 + 4];
            float4 b0 = *(const float4*)&Bs[k][tx * 8];
            float4 b1 = *(const float4*)&Bs[k][tx * 8 + 4];
            float ar[8] = {a0.x, a0.y, a0.z, a0.w, a1.x, a1.y, a1.z, a1.w};
            float br[8] = {b0.x, b0.y, b0.z, b0.w, b1.x, b1.y, b1.z, b1.w};
#pragma unroll
            for (int i = 0; i < 8; i++)
#pragma unroll
                for (int j = 0; j < 8; j++)
                    acc[i][j] += ar[i] * br[j];
        }
        __syncthreads();
    }

#pragma unroll
    for (int i = 0; i < 8; i++) {
        const int m = bm + ty * 8 + i;
#pragma unroll
        for (int j = 0; j < 8; j++) {
            const int n = bn + tx * 8 + j;
            if (permute) {
                // m = b*SEQ + s ; n = h*HD + d  ->  [(b*NH+h), s, d]
                const int b = m >> 11, s = m & 2047;
                const int h = n >> 7,  d = n & 127;
                C[((size_t)((b * NH + h) * SEQ + s)) * HD + d] = acc[i][j];
            } else {
                C[(size_t)m * N + n] = acc[i][j];
            }
        }
    }
}

// ---------------------------------------------------------------------------
// Flash-style causal attention. Q,K,V: [B*NH, S, HD]. Out: g_A [B, S, HID].
// 32x32 tiles, 256 threads. 8 threads per q-row own 16 output dims each.
// ---------------------------------------------------------------------------
#define AQ 32
#define AK 32

__global__ __launch_bounds__(256, 2)
void attn_kernel(const float* __restrict__ Q, const float* __restrict__ K,
                 const float* __restrict__ V, float* __restrict__ O)
{
    __shared__ float sQ[AQ][HD + PAD];    // stride 132: float4-aligned rows
    __shared__ float sKV[AK][HD + PAD];
    __shared__ float sS[AQ][AK + 1];      // scalar access only

    const int t  = threadIdx.x;
    const int qb = blockIdx.x;          // q tile (0..63)
    const int bh = blockIdx.y;          // 0..31
    const float scale = 0.08838834764831845f;   // 1/sqrt(128)

    const float* Qb = Q + (size_t)bh * SEQ * HD;
    const float* Kb = K + (size_t)bh * SEQ * HD;
    const float* Vb = V + (size_t)bh * SEQ * HD;

    // load Q tile (scaled)
    for (int i = t; i < AQ * (HD / 4); i += 256) {
        const int row = i / (HD / 4);
        const int col = (i % (HD / 4)) * 4;
        float4 v = *(const float4*)&Qb[(size_t)(qb * AQ + row) * HD + col];
        sQ[row][col + 0] = v.x * scale;
        sQ[row][col + 1] = v.y * scale;
        sQ[row][col + 2] = v.z * scale;
        sQ[row][col + 3] = v.w * scale;
    }

    // score-phase mapping: rows {sy, sy+16}, cols {sx, sx+16}
    const int sx = t & 15;
    const int sy = t >> 4;
    // softmax/PV mapping: row r, 8 lanes per row, lane owns d = qlane + 8*i
    const int r     = t >> 3;
    const int qlane = t & 7;

    float mrow = -CUDART_INF_F;
    float lrow = 0.f;
    float oacc[16];
#pragma unroll
    for (int i = 0; i < 16; i++) oacc[i] = 0.f;

    for (int kb = 0; kb <= qb; kb++) {
        __syncthreads();                       // prev PV done with sKV
        // load K tile
        for (int i = t; i < AK * (HD / 4); i += 256) {
            const int row = i / (HD / 4);
            const int col = (i % (HD / 4)) * 4;
            *(float4*)&sKV[row][col] =
                *(const float4*)&Kb[(size_t)(kb * AK + row) * HD + col];
        }
        __syncthreads();

        // scores: each thread 2x2
        float s00 = 0.f, s01 = 0.f, s10 = 0.f, s11 = 0.f;
#pragma unroll 4
        for (int d = 0; d < HD; d++) {
            const float q0 = sQ[sy][d];
            const float q1 = sQ[sy + 16][d];
            const float k0 = sKV[sx][d];
            const float k1 = sKV[sx + 16][d];
            s00 += q0 * k0;  s01 += q0 * k1;
            s10 += q1 * k0;  s11 += q1 * k1;
        }
        {
            const int qg = qb * AQ, kg = kb * AK;
            sS[sy][sx]           = (kg + sx      <= qg + sy)      ? s00 : -CUDART_INF_F;
            sS[sy][sx + 16]      = (kg + sx + 16 <= qg + sy)      ? s01 : -CUDART_INF_F;
            sS[sy + 16][sx]      = (kg + sx      <= qg + sy + 16) ? s10 : -CUDART_INF_F;
            sS[sy + 16][sx + 16] = (kg + sx + 16 <= qg + sy + 16) ? s11 : -CUDART_INF_F;
        }
        __syncthreads();                       // sS ready; sKV free

        // load V tile over sKV
        for (int i = t; i < AK * (HD / 4); i += 256) {
            const int row = i / (HD / 4);
            const int col = (i % (HD / 4)) * 4;
            *(float4*)&sKV[row][col] =
                *(const float4*)&Vb[(size_t)(kb * AK + row) * HD + col];
        }
        __syncthreads();

        // online softmax (8 lanes per row cooperate)
        float pm = -CUDART_INF_F;
#pragma unroll
        for (int i = 0; i < 4; i++)
            pm = fmaxf(pm, sS[r][qlane * 4 + i]);
#pragma unroll
        for (int o = 4; o >= 1; o >>= 1)
            pm = fmaxf(pm, __shfl_xor_sync(0xffffffffu, pm, o, 8));

        const float mnew = fmaxf(mrow, pm);
        const float corr = __expf(mrow - mnew);
        float psum = 0.f;
#pragma unroll
        for (int i = 0; i < 4; i++) {
            const int c = qlane * 4 + i;
            const float p = __expf(sS[r][c] - mnew);
            sS[r][c] = p;
            psum += p;
        }
        __syncwarp();                          // row lanes share warp
#pragma unroll
        for (int o = 4; o >= 1; o >>= 1)
            psum += __shfl_xor_sync(0xffffffffu, psum, o, 8);

        lrow = lrow * corr + psum;
        mrow = mnew;
#pragma unroll
        for (int i = 0; i < 16; i++) oacc[i] *= corr;

        // O += P * V
#pragma unroll 8
        for (int c = 0; c < AK; c++) {
            const float p = sS[r][c];
#pragma unroll
            for (int i = 0; i < 16; i++)
                oacc[i] += p * sKV[c][qlane + i * 8];
        }
    }

    // write normalized output: [B, S, HID] with col = h*HD + d
    const float inv = 1.f / lrow;
    const int b = bh >> 4, h = bh & 15;
    const int s = qb * AQ + r;
    float* Orow = O + ((size_t)(b * SEQ + s)) * HID + h * HD;
#pragma unroll
    for (int i = 0; i < 16; i++)
        Orow[qlane + i * 8] = oacc[i] * inv;
}

// ---------------------------------------------------------------------------
extern "C" void kernel_launch(void* const* d_in, const int* in_sizes, int n_in,
                              void* d_out, int out_size)
{
    const float* x  = (const float*)d_in[0];
    const float* Wq = (const float*)d_in[1];
    const float* Wk = (const float*)d_in[2];
    const float* Wv = (const float*)d_in[3];
    const float* Wo = (const float*)d_in[4];

    float *Qp, *Kp, *Vp, *Ap;
    cudaGetSymbolAddress((void**)&Qp, g_Q);
    cudaGetSymbolAddress((void**)&Kp, g_K);
    cudaGetSymbolAddress((void**)&Vp, g_V);
    cudaGetSymbolAddress((void**)&Ap, g_A);

    dim3 gg(HID / GBN, MTOT / GBM);     // (16, 32)
    sgemm_kernel<<<gg, 256>>>(x, Wq, Qp, MTOT, HID, HID, 1);
    sgemm_kernel<<<gg, 256>>>(x, Wk, Kp, MTOT, HID, HID, 1);
    sgemm_kernel<<<gg, 256>>>(x, Wv, Vp, MTOT, HID, HID, 1);

    attn_kernel<<<dim3(SEQ / AQ, BATCH * NH), 256>>>(Qp, Kp, Vp, Ap);

    sgemm_kernel<<<gg, 256>>>(Ap, Wo, (float*)d_out, MTOT, HID, HID, 0);
}

// round 4
// speedup vs baseline: 1.8001x; 1.8001x over previous
#include <cuda_runtime.h>
#include <cuda_bf16.h>
#include <math_constants.h>
#include <cstdint>

// ---------------------------------------------------------------------------
// MultiHeadAttention: x[2,2048,2048] fp32, 4x W[2048,2048]
// Round 4: GEMMs via mma.sync tf32 (sm_80-class PTX; tcgen05 is rejected by
//          this harness's compute_103 virtual arch). Attention SIMT fp32.
// ---------------------------------------------------------------------------

#define BATCH   2
#define SEQ     2048
#define HID     2048
#define NH      16
#define HD      128
#define MTOT    (BATCH * SEQ)          // 4096
#define PAD     4

// scratch
__device__ float g_Q[MTOT * HID];
__device__ float g_K[MTOT * HID];
__device__ float g_V[MTOT * HID];
__device__ float g_A[MTOT * HID];
__device__ float g_WT[4ull * HID * HID];   // transposed weights [N,K]

// ---------------------------------------------------------------------------
__device__ __forceinline__ uint32_t f2tf32(float x) {
    uint32_t r;
    asm("cvt.rna.tf32.f32 %0, %1;" : "=r"(r) : "f"(x));
    return r;
}

__device__ __forceinline__ void mma_tf32(float* d, const uint32_t* a, const uint32_t* b) {
    asm volatile(
        "mma.sync.aligned.m16n8k8.row.col.f32.tf32.tf32.f32 "
        "{%0,%1,%2,%3}, {%4,%5,%6,%7}, {%8,%9}, {%0,%1,%2,%3};"
        : "+f"(d[0]), "+f"(d[1]), "+f"(d[2]), "+f"(d[3])
        : "r"(a[0]), "r"(a[1]), "r"(a[2]), "r"(a[3]), "r"(b[0]), "r"(b[1]));
}

// ---------------------------------------------------------------------------
// Weight transpose: Wt[n, k] = W[k, n]   (2048 x 2048)
// ---------------------------------------------------------------------------
__global__ __launch_bounds__(256)
void transpose2048(const float* __restrict__ W, float* __restrict__ Wt)
{
    __shared__ float tile[32][33];
    const int bx = blockIdx.x * 32;   // n
    const int by = blockIdx.y * 32;   // k
    const int tx = threadIdx.x, ty = threadIdx.y;

    for (int i = ty; i < 32; i += 8)
        tile[i][tx] = W[(size_t)(by + i) * HID + bx + tx];
    __syncthreads();
    for (int i = ty; i < 32; i += 8)
        Wt[(size_t)(bx + i) * HID + by + tx] = tile[tx][i];
}

// ---------------------------------------------------------------------------
// tf32 mma GEMM: C[4096,2048] = A[4096,2048] * Bt[2048,2048]^T
// Bt is [N,K] row-major. Tile 128x128x32, 8 warps (2M x 4N), warp 64x32.
// permute=1: write C into [B*NH, S, HD] (fused head transpose).
// ---------------------------------------------------------------------------
#define TBM 128
#define TBN 128
#define TBK 32
#define KCHUNKS (HID / TBK)            // 64
#define SROW 36                        // smem row stride (floats): conflict-free frags

__global__ __launch_bounds__(256)
void gemm_tf32_mma(const float* __restrict__ A, const float* __restrict__ Bt,
                   float* __restrict__ C, int permute)
{
    __shared__ uint32_t sA[TBM * SROW];
    __shared__ uint32_t sB[TBN * SROW];

    const int t    = threadIdx.x;
    const int wid  = t >> 5;
    const int lane = t & 31;
    const int m0   = blockIdx.y * TBM;
    const int n0   = blockIdx.x * TBN;

    const int grp  = lane >> 2;        // 0..7
    const int tid4 = lane & 3;         // 0..3
    const int wm   = (wid & 1) * 64;   // warp M offset
    const int wn   = (wid >> 1) * 32;  // warp N offset

    // global loader mapping: 256 threads cover 32 rows x 8 float4; 4 passes
    const int lrow   = (wid << 2) + (lane >> 3);   // 0..31
    const int lcol16 = lane & 7;                   // float4 index in 32-float row

    const float* Ag = A  + (size_t)(m0 + lrow) * HID + lcol16 * 4;
    const float* Bg = Bt + (size_t)(n0 + lrow) * HID + lcol16 * 4;

    float acc[4][4][4];
#pragma unroll
    for (int i = 0; i < 4; i++)
#pragma unroll
        for (int j = 0; j < 4; j++)
#pragma unroll
            for (int r = 0; r < 4; r++) acc[i][j][r] = 0.f;

    float4 ra[4], rb[4];
#pragma unroll
    for (int p = 0; p < 4; p++) {
        ra[p] = *(const float4*)(Ag + (size_t)p * 32 * HID);
        rb[p] = *(const float4*)(Bg + (size_t)p * 32 * HID);
    }

    for (int c = 0; c < KCHUNKS; ++c) {
        // store current chunk to smem (tf32-rounded)
#pragma unroll
        for (int p = 0; p < 4; p++) {
            const int r = lrow + p * 32;
            uint32_t* da = &sA[r * SROW + lcol16 * 4];
            uint32_t* db = &sB[r * SROW + lcol16 * 4];
            da[0] = f2tf32(ra[p].x); da[1] = f2tf32(ra[p].y);
            da[2] = f2tf32(ra[p].z); da[3] = f2tf32(ra[p].w);
            db[0] = f2tf32(rb[p].x); db[1] = f2tf32(rb[p].y);
            db[2] = f2tf32(rb[p].z); db[3] = f2tf32(rb[p].w);
        }
        __syncthreads();

        // prefetch next chunk
        if (c + 1 < KCHUNKS) {
            const int ko = (c + 1) * TBK;
#pragma unroll
            for (int p = 0; p < 4; p++) {
                ra[p] = *(const float4*)(Ag + (size_t)p * 32 * HID + ko);
                rb[p] = *(const float4*)(Bg + (size_t)p * 32 * HID + ko);
            }
        }

        // 4 k-steps of 8
#pragma unroll
        for (int ks = 0; ks < 4; ks++) {
            const int k0 = ks * 8;
            uint32_t af[4][4], bf[4][2];
#pragma unroll
            for (int mt = 0; mt < 4; mt++) {
                const int r = wm + mt * 16 + grp;
                af[mt][0] = sA[r * SROW + k0 + tid4];
                af[mt][1] = sA[(r + 8) * SROW + k0 + tid4];
                af[mt][2] = sA[r * SROW + k0 + tid4 + 4];
                af[mt][3] = sA[(r + 8) * SROW + k0 + tid4 + 4];
            }
#pragma unroll
            for (int nt = 0; nt < 4; nt++) {
                const int n = wn + nt * 8 + grp;
                bf[nt][0] = sB[n * SROW + k0 + tid4];
                bf[nt][1] = sB[n * SROW + k0 + tid4 + 4];
            }
#pragma unroll
            for (int mt = 0; mt < 4; mt++)
#pragma unroll
                for (int nt = 0; nt < 4; nt++)
                    mma_tf32(acc[mt][nt], af[mt], bf[nt]);
        }
        __syncthreads();
    }

    // epilogue: thread owns (grp, grp+8) x (2*tid4, 2*tid4+1) of each 16x8 tile
#pragma unroll
    for (int mt = 0; mt < 4; mt++) {
#pragma unroll
        for (int nt = 0; nt < 4; nt++) {
            const int row0 = m0 + wm + mt * 16 + grp;
            const int col  = n0 + wn + nt * 8 + tid4 * 2;
#pragma unroll
            for (int h = 0; h < 2; h++) {
                const int row = row0 + h * 8;
                float2 v = make_float2(acc[mt][nt][h * 2], acc[mt][nt][h * 2 + 1]);
                if (permute) {
                    const int b = row >> 11, s = row & 2047;
                    const int hh = col >> 7, dc = col & 127;
                    *(float2*)&C[((size_t)((b * NH + hh) * SEQ + s)) * HD + dc] = v;
                } else {
                    *(float2*)&C[(size_t)row * HID + col] = v;
                }
            }
        }
    }
}

// ---------------------------------------------------------------------------
// Flash-style causal attention (unchanged, passing).
// ---------------------------------------------------------------------------
#define AQ 32
#define AK 32

__global__ __launch_bounds__(256, 2)
void attn_kernel(const float* __restrict__ Q, const float* __restrict__ K,
                 const float* __restrict__ V, float* __restrict__ O)
{
    __shared__ float sQ[AQ][HD + PAD];
    __shared__ float sKV[AK][HD + PAD];
    __shared__ float sS[AQ][AK + 1];

    const int t  = threadIdx.x;
    const int qb = blockIdx.x;
    const int bh = blockIdx.y;
    const float scale = 0.08838834764831845f;

    const float* Qb = Q + (size_t)bh * SEQ * HD;
    const float* Kb = K + (size_t)bh * SEQ * HD;
    const float* Vb = V + (size_t)bh * SEQ * HD;

    for (int i = t; i < AQ * (HD / 4); i += 256) {
        const int row = i / (HD / 4);
        const int col = (i % (HD / 4)) * 4;
        float4 v = *(const float4*)&Qb[(size_t)(qb * AQ + row) * HD + col];
        sQ[row][col + 0] = v.x * scale;
        sQ[row][col + 1] = v.y * scale;
        sQ[row][col + 2] = v.z * scale;
        sQ[row][col + 3] = v.w * scale;
    }

    const int sx = t & 15;
    const int sy = t >> 4;
    const int r     = t >> 3;
    const int qlane = t & 7;

    float mrow = -CUDART_INF_F;
    float lrow = 0.f;
    float oacc[16];
#pragma unroll
    for (int i = 0; i < 16; i++) oacc[i] = 0.f;

    for (int kb = 0; kb <= qb; kb++) {
        __syncthreads();
        for (int i = t; i < AK * (HD / 4); i += 256) {
            const int row = i / (HD / 4);
            const int col = (i % (HD / 4)) * 4;
            *(float4*)&sKV[row][col] =
                *(const float4*)&Kb[(size_t)(kb * AK + row) * HD + col];
        }
        __syncthreads();

        float s00 = 0.f, s01 = 0.f, s10 = 0.f, s11 = 0.f;
#pragma unroll 4
        for (int d = 0; d < HD; d++) {
            const float q0 = sQ[sy][d];
            const float q1 = sQ[sy + 16][d];
            const float k0 = sKV[sx][d];
            const float k1 = sKV[sx + 16][d];
            s00 += q0 * k0;  s01 += q0 * k1;
            s10 += q1 * k0;  s11 += q1 * k1;
        }
        {
            const int qg = qb * AQ, kg = kb * AK;
            sS[sy][sx]           = (kg + sx      <= qg + sy)      ? s00 : -CUDART_INF_F;
            sS[sy][sx + 16]      = (kg + sx + 16 <= qg + sy)      ? s01 : -CUDART_INF_F;
            sS[sy + 16][sx]      = (kg + sx      <= qg + sy + 16) ? s10 : -CUDART_INF_F;
            sS[sy + 16][sx + 16] = (kg + sx + 16 <= qg + sy + 16) ? s11 : -CUDART_INF_F;
        }
        __syncthreads();

        for (int i = t; i < AK * (HD / 4); i += 256) {
            const int row = i / (HD / 4);
            const int col = (i % (HD / 4)) * 4;
            *(float4*)&sKV[row][col] =
                *(const float4*)&Vb[(size_t)(kb * AK + row) * HD + col];
        }
        __syncthreads();

        float pm = -CUDART_INF_F;
#pragma unroll
        for (int i = 0; i < 4; i++)
            pm = fmaxf(pm, sS[r][qlane * 4 + i]);
#pragma unroll
        for (int o = 4; o >= 1; o >>= 1)
            pm = fmaxf(pm, __shfl_xor_sync(0xffffffffu, pm, o, 8));

        const float mnew = fmaxf(mrow, pm);
        const float corr = __expf(mrow - mnew);
        float psum = 0.f;
#pragma unroll
        for (int i = 0; i < 4; i++) {
            const int c = qlane * 4 + i;
            const float p = __expf(sS[r][c] - mnew);
            sS[r][c] = p;
            psum += p;
        }
        __syncwarp();
#pragma unroll
        for (int o = 4; o >= 1; o >>= 1)
            psum += __shfl_xor_sync(0xffffffffu, psum, o, 8);

        lrow = lrow * corr + psum;
        mrow = mnew;
#pragma unroll
        for (int i = 0; i < 16; i++) oacc[i] *= corr;

#pragma unroll 8
        for (int c = 0; c < AK; c++) {
            const float p = sS[r][c];
#pragma unroll
            for (int i = 0; i < 16; i++)
                oacc[i] += p * sKV[c][qlane + i * 8];
        }
    }

    const float inv = 1.f / lrow;
    const int b = bh >> 4, h = bh & 15;
    const int s = qb * AQ + r;
    float* Orow = O + ((size_t)(b * SEQ + s)) * HID + h * HD;
#pragma unroll
    for (int i = 0; i < 16; i++)
        Orow[qlane + i * 8] = oacc[i] * inv;
}

// ---------------------------------------------------------------------------
extern "C" void kernel_launch(void* const* d_in, const int* in_sizes, int n_in,
                              void* d_out, int out_size)
{
    const float* x  = (const float*)d_in[0];
    const float* Wq = (const float*)d_in[1];
    const float* Wk = (const float*)d_in[2];
    const float* Wv = (const float*)d_in[3];
    const float* Wo = (const float*)d_in[4];

    float *Qp, *Kp, *Vp, *Ap, *WTp;
    cudaGetSymbolAddress((void**)&Qp,  g_Q);
    cudaGetSymbolAddress((void**)&Kp,  g_K);
    cudaGetSymbolAddress((void**)&Vp,  g_V);
    cudaGetSymbolAddress((void**)&Ap,  g_A);
    cudaGetSymbolAddress((void**)&WTp, g_WT);

    const size_t WSZ = (size_t)HID * HID;
    dim3 tg(64, 64), tb(32, 8);
    transpose2048<<<tg, tb>>>(Wq, WTp + 0 * WSZ);
    transpose2048<<<tg, tb>>>(Wk, WTp + 1 * WSZ);
    transpose2048<<<tg, tb>>>(Wv, WTp + 2 * WSZ);
    transpose2048<<<tg, tb>>>(Wo, WTp + 3 * WSZ);

    dim3 gg(HID / TBN, MTOT / TBM);   // (16, 32)
    gemm_tf32_mma<<<gg, 256>>>(x, WTp + 0 * WSZ, Qp, 1);
    gemm_tf32_mma<<<gg, 256>>>(x, WTp + 1 * WSZ, Kp, 1);
    gemm_tf32_mma<<<gg, 256>>>(x, WTp + 2 * WSZ, Vp, 1);

    attn_kernel<<<dim3(SEQ / AQ, BATCH * NH), 256>>>(Qp, Kp, Vp, Ap);

    gemm_tf32_mma<<<gg, 256>>>(Ap, WTp + 3 * WSZ, (float*)d_out, 0);
}

// round 5
// speedup vs baseline: 3.7682x; 2.0933x over previous
#include <cuda_runtime.h>
#include <cuda_bf16.h>
#include <math_constants.h>
#include <cstdint>

// ---------------------------------------------------------------------------
// MultiHeadAttention: x[2,2048,2048] fp32, 4x W[2048,2048]
// Round 5: attention moved to mma.sync tf32 (flash-style, 64-row q tiles).
//          GEMMs unchanged from round 4 (mma.sync tf32).
// ---------------------------------------------------------------------------

#define BATCH   2
#define SEQ     2048
#define HID     2048
#define NH      16
#define HD      128
#define MTOT    (BATCH * SEQ)          // 4096

// scratch
__device__ float g_Q[MTOT * HID];
__device__ float g_K[MTOT * HID];
__device__ float g_V[MTOT * HID];
__device__ float g_A[MTOT * HID];
__device__ float g_WT[4ull * HID * HID];   // transposed weights [N,K]

// ---------------------------------------------------------------------------
__device__ __forceinline__ uint32_t f2tf32(float x) {
    uint32_t r;
    asm("cvt.rna.tf32.f32 %0, %1;" : "=r"(r) : "f"(x));
    return r;
}

__device__ __forceinline__ void mma_tf32(float* d, const uint32_t* a, const uint32_t* b) {
    asm volatile(
        "mma.sync.aligned.m16n8k8.row.col.f32.tf32.tf32.f32 "
        "{%0,%1,%2,%3}, {%4,%5,%6,%7}, {%8,%9}, {%0,%1,%2,%3};"
        : "+f"(d[0]), "+f"(d[1]), "+f"(d[2]), "+f"(d[3])
        : "r"(a[0]), "r"(a[1]), "r"(a[2]), "r"(a[3]), "r"(b[0]), "r"(b[1]));
}

// swizzled smem indexers (uint32 element index)
__device__ __forceinline__ int swz128(int row, int col) {    // [*][128] arrays
    return row * 128 + (((((col >> 2) ^ row) & 7) | ((col >> 2) & ~7)) << 2) + (col & 3);
}
__device__ __forceinline__ int swz64(int row, int col) {     // [*][64] arrays
    return row * 64 + (((((col >> 2) ^ row) & 7) | ((col >> 2) & ~7)) << 2) + (col & 3);
}

// ---------------------------------------------------------------------------
// Weight transpose: Wt[n, k] = W[k, n]   (2048 x 2048)
// ---------------------------------------------------------------------------
__global__ __launch_bounds__(256)
void transpose2048(const float* __restrict__ W, float* __restrict__ Wt)
{
    __shared__ float tile[32][33];
    const int bx = blockIdx.x * 32;
    const int by = blockIdx.y * 32;
    const int tx = threadIdx.x, ty = threadIdx.y;

    for (int i = ty; i < 32; i += 8)
        tile[i][tx] = W[(size_t)(by + i) * HID + bx + tx];
    __syncthreads();
    for (int i = ty; i < 32; i += 8)
        Wt[(size_t)(bx + i) * HID + by + tx] = tile[tx][i];
}

// ---------------------------------------------------------------------------
// tf32 mma GEMM (unchanged from round 4, passing).
// ---------------------------------------------------------------------------
#define TBM 128
#define TBN 128
#define TBK 32
#define KCHUNKS (HID / TBK)
#define SROW 36

__global__ __launch_bounds__(256)
void gemm_tf32_mma(const float* __restrict__ A, const float* __restrict__ Bt,
                   float* __restrict__ C, int permute)
{
    __shared__ uint32_t sA[TBM * SROW];
    __shared__ uint32_t sB[TBN * SROW];

    const int t    = threadIdx.x;
    const int wid  = t >> 5;
    const int lane = t & 31;
    const int m0   = blockIdx.y * TBM;
    const int n0   = blockIdx.x * TBN;

    const int grp  = lane >> 2;
    const int tid4 = lane & 3;
    const int wm   = (wid & 1) * 64;
    const int wn   = (wid >> 1) * 32;

    const int lrow   = (wid << 2) + (lane >> 3);
    const int lcol16 = lane & 7;

    const float* Ag = A  + (size_t)(m0 + lrow) * HID + lcol16 * 4;
    const float* Bg = Bt + (size_t)(n0 + lrow) * HID + lcol16 * 4;

    float acc[4][4][4];
#pragma unroll
    for (int i = 0; i < 4; i++)
#pragma unroll
        for (int j = 0; j < 4; j++)
#pragma unroll
            for (int r = 0; r < 4; r++) acc[i][j][r] = 0.f;

    float4 ra[4], rb[4];
#pragma unroll
    for (int p = 0; p < 4; p++) {
        ra[p] = *(const float4*)(Ag + (size_t)p * 32 * HID);
        rb[p] = *(const float4*)(Bg + (size_t)p * 32 * HID);
    }

    for (int c = 0; c < KCHUNKS; ++c) {
#pragma unroll
        for (int p = 0; p < 4; p++) {
            const int r = lrow + p * 32;
            uint32_t* da = &sA[r * SROW + lcol16 * 4];
            uint32_t* db = &sB[r * SROW + lcol16 * 4];
            da[0] = f2tf32(ra[p].x); da[1] = f2tf32(ra[p].y);
            da[2] = f2tf32(ra[p].z); da[3] = f2tf32(ra[p].w);
            db[0] = f2tf32(rb[p].x); db[1] = f2tf32(rb[p].y);
            db[2] = f2tf32(rb[p].z); db[3] = f2tf32(rb[p].w);
        }
        __syncthreads();

        if (c + 1 < KCHUNKS) {
            const int ko = (c + 1) * TBK;
#pragma unroll
            for (int p = 0; p < 4; p++) {
                ra[p] = *(const float4*)(Ag + (size_t)p * 32 * HID + ko);
                rb[p] = *(const float4*)(Bg + (size_t)p * 32 * HID + ko);
            }
        }

#pragma unroll
        for (int ks = 0; ks < 4; ks++) {
            const int k0 = ks * 8;
            uint32_t af[4][4], bf[4][2];
#pragma unroll
            for (int mt = 0; mt < 4; mt++) {
                const int r = wm + mt * 16 + grp;
                af[mt][0] = sA[r * SROW + k0 + tid4];
                af[mt][1] = sA[(r + 8) * SROW + k0 + tid4];
                af[mt][2] = sA[r * SROW + k0 + tid4 + 4];
                af[mt][3] = sA[(r + 8) * SROW + k0 + tid4 + 4];
            }
#pragma unroll
            for (int nt = 0; nt < 4; nt++) {
                const int n = wn + nt * 8 + grp;
                bf[nt][0] = sB[n * SROW + k0 + tid4];
                bf[nt][1] = sB[n * SROW + k0 + tid4 + 4];
            }
#pragma unroll
            for (int mt = 0; mt < 4; mt++)
#pragma unroll
                for (int nt = 0; nt < 4; nt++)
                    mma_tf32(acc[mt][nt], af[mt], bf[nt]);
        }
        __syncthreads();
    }

#pragma unroll
    for (int mt = 0; mt < 4; mt++) {
#pragma unroll
        for (int nt = 0; nt < 4; nt++) {
            const int row0 = m0 + wm + mt * 16 + grp;
            const int col  = n0 + wn + nt * 8 + tid4 * 2;
#pragma unroll
            for (int h = 0; h < 2; h++) {
                const int row = row0 + h * 8;
                float2 v = make_float2(acc[mt][nt][h * 2], acc[mt][nt][h * 2 + 1]);
                if (permute) {
                    const int b = row >> 11, s = row & 2047;
                    const int hh = col >> 7, dc = col & 127;
                    *(float2*)&C[((size_t)((b * NH + hh) * SEQ + s)) * HD + dc] = v;
                } else {
                    *(float2*)&C[(size_t)row * HID + col] = v;
                }
            }
        }
    }
}

// ---------------------------------------------------------------------------
// Tensor-core flash attention. Q,K,V: [B*NH, S, HD] fp32. Out: g_A [B,S,HID].
// CTA: 64 q-rows, 128 threads (4 warps x 16 rows). KV tile 64.
// Dynamic smem 80KB: sQ[64][128] | union(sK[64][128], sVT[128][64]) | sP[64][64]
// ---------------------------------------------------------------------------
__global__ __launch_bounds__(128)
void attn_mma_kernel(const float* __restrict__ Q, const float* __restrict__ K,
                     const float* __restrict__ V, float* __restrict__ O)
{
    extern __shared__ uint32_t dsm[];
    uint32_t* sQ  = dsm;            // 8192  u32
    uint32_t* sKV = dsm + 8192;     // 8192  u32 (K or V^T)
    uint32_t* sP  = dsm + 16384;    // 4096  u32

    const int t    = threadIdx.x;
    const int w    = t >> 5;
    const int lane = t & 31;
    const int grp  = lane >> 2;
    const int tid4 = lane & 3;
    const int qb   = blockIdx.x;     // 0..31 (64-row q tiles)
    const int bh   = blockIdx.y;     // 0..31
    const float scale = 0.08838834764831845f;   // 1/sqrt(128)

    const float* Qb = Q + ((size_t)bh * SEQ + qb * 64) * HD;
    const float* Kb = K + (size_t)bh * SEQ * HD;
    const float* Vb = V + (size_t)bh * SEQ * HD;

    // ---- load Q tile (scaled, tf32, swizzled) ----
#pragma unroll
    for (int p = 0; p < 16; p++) {
        const int row = p * 4 + w;
        float4 v = *(const float4*)&Qb[(size_t)row * HD + lane * 4];
        uint32_t* d = &sQ[row * 128 + ((lane ^ (row & 7)) << 2)];
        d[0] = f2tf32(v.x * scale); d[1] = f2tf32(v.y * scale);
        d[2] = f2tf32(v.z * scale); d[3] = f2tf32(v.w * scale);
    }

    const int r0 = w * 16 + grp;      // this thread's first q row (local)
    float m0 = -CUDART_INF_F, m1 = -CUDART_INF_F;
    float l0 = 0.f, l1 = 0.f;
    float o[16][4];
#pragma unroll
    for (int nt = 0; nt < 16; nt++)
#pragma unroll
        for (int r = 0; r < 4; r++) o[nt][r] = 0.f;

    for (int kb = 0; kb <= qb; kb++) {
        // ---- load K tile (tf32, swizzled) ----
#pragma unroll
        for (int p = 0; p < 16; p++) {
            const int row = p * 4 + w;
            float4 v = *(const float4*)&Kb[(size_t)(kb * 64 + row) * HD + lane * 4];
            uint32_t* d = &sKV[row * 128 + ((lane ^ (row & 7)) << 2)];
            d[0] = f2tf32(v.x); d[1] = f2tf32(v.y);
            d[2] = f2tf32(v.z); d[3] = f2tf32(v.w);
        }
        __syncthreads();

        // ---- S = Q K^T (per warp: 16 x 64) ----
        float s[8][4];
#pragma unroll
        for (int nt = 0; nt < 8; nt++)
#pragma unroll
            for (int r = 0; r < 4; r++) s[nt][r] = 0.f;

#pragma unroll
        for (int ks = 0; ks < 16; ks++) {
            const int k0 = ks * 8;
            uint32_t a[4];
            a[0] = sQ[swz128(r0,     k0 + tid4)];
            a[1] = sQ[swz128(r0 + 8, k0 + tid4)];
            a[2] = sQ[swz128(r0,     k0 + tid4 + 4)];
            a[3] = sQ[swz128(r0 + 8, k0 + tid4 + 4)];
#pragma unroll
            for (int nt = 0; nt < 8; nt++) {
                uint32_t b[2];
                b[0] = sKV[swz128(nt * 8 + grp, k0 + tid4)];
                b[1] = sKV[swz128(nt * 8 + grp, k0 + tid4 + 4)];
                mma_tf32(s[nt], a, b);
            }
        }
        __syncthreads();    // K fully consumed -> sKV reusable for V^T

        // ---- causal mask (diagonal tile only) ----
        if (kb == qb) {
            const int rg0 = qb * 64 + r0;
            const int rg1 = rg0 + 8;
#pragma unroll
            for (int nt = 0; nt < 8; nt++) {
                const int c0 = kb * 64 + nt * 8 + 2 * tid4;
                if (c0     > rg0) s[nt][0] = -CUDART_INF_F;
                if (c0 + 1 > rg0) s[nt][1] = -CUDART_INF_F;
                if (c0     > rg1) s[nt][2] = -CUDART_INF_F;
                if (c0 + 1 > rg1) s[nt][3] = -CUDART_INF_F;
            }
        }

        // ---- load V^T tile (tf32, swizzled) over sKV ----
        {
            const int kv = lane + 32 * (w & 1);
#pragma unroll
            for (int p = 0; p < 16; p++) {
                const int hc = 2 * p + (w >> 1);
                float4 v = *(const float4*)&Vb[(size_t)(kb * 64 + kv) * HD + hc * 4];
                const int hd0 = 4 * hc;
                sKV[(hd0    ) * 64 + ((((kv >> 2) ^ ( hd0      & 7)) << 2)) + (kv & 3)] = f2tf32(v.x);
                sKV[(hd0 + 1) * 64 + ((((kv >> 2) ^ ((hd0 + 1) & 7)) << 2)) + (kv & 3)] = f2tf32(v.y);
                sKV[(hd0 + 2) * 64 + ((((kv >> 2) ^ ((hd0 + 2) & 7)) << 2)) + (kv & 3)] = f2tf32(v.z);
                sKV[(hd0 + 3) * 64 + ((((kv >> 2) ^ ((hd0 + 3) & 7)) << 2)) + (kv & 3)] = f2tf32(v.w);
            }
        }

        // ---- online softmax on fragments ----
        float rm0 = -CUDART_INF_F, rm1 = -CUDART_INF_F;
#pragma unroll
        for (int nt = 0; nt < 8; nt++) {
            rm0 = fmaxf(rm0, fmaxf(s[nt][0], s[nt][1]));
            rm1 = fmaxf(rm1, fmaxf(s[nt][2], s[nt][3]));
        }
        rm0 = fmaxf(rm0, __shfl_xor_sync(0xffffffffu, rm0, 1));
        rm0 = fmaxf(rm0, __shfl_xor_sync(0xffffffffu, rm0, 2));
        rm1 = fmaxf(rm1, __shfl_xor_sync(0xffffffffu, rm1, 1));
        rm1 = fmaxf(rm1, __shfl_xor_sync(0xffffffffu, rm1, 2));

        const float mn0 = fmaxf(m0, rm0);
        const float mn1 = fmaxf(m1, rm1);
        const float cf0 = __expf(m0 - mn0);
        const float cf1 = __expf(m1 - mn1);
        m0 = mn0; m1 = mn1;

        float ps0 = 0.f, ps1 = 0.f;
#pragma unroll
        for (int nt = 0; nt < 8; nt++) {
            const float p00 = __expf(s[nt][0] - m0);
            const float p01 = __expf(s[nt][1] - m0);
            const float p10 = __expf(s[nt][2] - m1);
            const float p11 = __expf(s[nt][3] - m1);
            ps0 += p00 + p01;
            ps1 += p10 + p11;
            uint2 u0 = make_uint2(f2tf32(p00), f2tf32(p01));
            uint2 u1 = make_uint2(f2tf32(p10), f2tf32(p11));
            *(uint2*)&sP[swz64(r0,     nt * 8 + 2 * tid4)] = u0;
            *(uint2*)&sP[swz64(r0 + 8, nt * 8 + 2 * tid4)] = u1;
        }
        ps0 += __shfl_xor_sync(0xffffffffu, ps0, 1);
        ps0 += __shfl_xor_sync(0xffffffffu, ps0, 2);
        ps1 += __shfl_xor_sync(0xffffffffu, ps1, 1);
        ps1 += __shfl_xor_sync(0xffffffffu, ps1, 2);
        l0 = l0 * cf0 + ps0;
        l1 = l1 * cf1 + ps1;

#pragma unroll
        for (int nt = 0; nt < 16; nt++) {
            o[nt][0] *= cf0; o[nt][1] *= cf0;
            o[nt][2] *= cf1; o[nt][3] *= cf1;
        }

        __syncthreads();    // V^T visible to all warps (and own-warp sP ordered)

        // ---- O += P V (per warp: 16 x 128, k=64) ----
#pragma unroll
        for (int kt = 0; kt < 8; kt++) {
            const int k0 = kt * 8;
            uint32_t a[4];
            a[0] = sP[swz64(r0,     k0 + tid4)];
            a[1] = sP[swz64(r0 + 8, k0 + tid4)];
            a[2] = sP[swz64(r0,     k0 + tid4 + 4)];
            a[3] = sP[swz64(r0 + 8, k0 + tid4 + 4)];
#pragma unroll
            for (int nt = 0; nt < 16; nt++) {
                uint32_t b[2];
                b[0] = sKV[swz64(nt * 8 + grp, k0 + tid4)];
                b[1] = sKV[swz64(nt * 8 + grp, k0 + tid4 + 4)];
                mma_tf32(o[nt], a, b);
            }
        }
        __syncthreads();    // V^T consumed before next K store
    }

    // ---- epilogue: normalize + store to g_A [B, S, HID] ----
    const int bb = bh >> 4, hh = bh & 15;
    const float i0 = 1.f / l0;
    const float i1 = 1.f / l1;
    const int sg = qb * 64 + r0;
#pragma unroll
    for (int nt = 0; nt < 16; nt++) {
        const int col = hh * 128 + nt * 8 + 2 * tid4;
        float2 v0 = make_float2(o[nt][0] * i0, o[nt][1] * i0);
        float2 v1 = make_float2(o[nt][2] * i1, o[nt][3] * i1);
        *(float2*)&O[((size_t)(bb * SEQ + sg    )) * HID + col] = v0;
        *(float2*)&O[((size_t)(bb * SEQ + sg + 8)) * HID + col] = v1;
    }
}

#define ATTN_SMEM_BYTES (20480 * 4)   // 80 KB

// ---------------------------------------------------------------------------
extern "C" void kernel_launch(void* const* d_in, const int* in_sizes, int n_in,
                              void* d_out, int out_size)
{
    const float* x  = (const float*)d_in[0];
    const float* Wq = (const float*)d_in[1];
    const float* Wk = (const float*)d_in[2];
    const float* Wv = (const float*)d_in[3];
    const float* Wo = (const float*)d_in[4];

    float *Qp, *Kp, *Vp, *Ap, *WTp;
    cudaGetSymbolAddress((void**)&Qp,  g_Q);
    cudaGetSymbolAddress((void**)&Kp,  g_K);
    cudaGetSymbolAddress((void**)&Vp,  g_V);
    cudaGetSymbolAddress((void**)&Ap,  g_A);
    cudaGetSymbolAddress((void**)&WTp, g_WT);

    cudaFuncSetAttribute(attn_mma_kernel,
                         cudaFuncAttributeMaxDynamicSharedMemorySize,
                         ATTN_SMEM_BYTES);

    const size_t WSZ = (size_t)HID * HID;
    dim3 tg(64, 64), tb(32, 8);
    transpose2048<<<tg, tb>>>(Wq, WTp + 0 * WSZ);
    transpose2048<<<tg, tb>>>(Wk, WTp + 1 * WSZ);
    transpose2048<<<tg, tb>>>(Wv, WTp + 2 * WSZ);
    transpose2048<<<tg, tb>>>(Wo, WTp + 3 * WSZ);

    dim3 gg(HID / TBN, MTOT / TBM);
    gemm_tf32_mma<<<gg, 256>>>(x, WTp + 0 * WSZ, Qp, 1);
    gemm_tf32_mma<<<gg, 256>>>(x, WTp + 1 * WSZ, Kp, 1);
    gemm_tf32_mma<<<gg, 256>>>(x, WTp + 2 * WSZ, Vp, 1);

    attn_mma_kernel<<<dim3(SEQ / 64, BATCH * NH), 128, ATTN_SMEM_BYTES>>>(Qp, Kp, Vp, Ap);

    gemm_tf32_mma<<<gg, 256>>>(Ap, WTp + 3 * WSZ, (float*)d_out, 0);
}